// round 14
// baseline (speedup 1.0000x reference)
#include <cuda_runtime.h>
#include <cstdint>
#include <math.h>

#define BATCH   8
#define NNODES  2048
#define FDIM    256
#define HEADS   4
#define HD      256
#define MTOT    (BATCH*NNODES)

// ---- scratch ----
__device__ float g_WhT[(size_t)MTOT * HD];  // Wh TRANSPOSED: [b][feat][node], tf32-rounded
__device__ float g_e[MTOT * HEADS];
__device__ float g_att[MTOT];
__device__ float g_mx[BATCH * HEADS];
__device__ float g_inv[BATCH * HEADS];

// ================= helpers =================
__device__ __forceinline__ uint32_t smem_u32(const void* p) {
    uint32_t a;
    asm("{ .reg .u64 t; cvta.to.shared.u64 t, %1; cvt.u32.u64 %0, t; }" : "=r"(a) : "l"(p));
    return a;
}
__device__ __forceinline__ float tf32_rna(float x) {
    uint32_t u;
    asm("cvt.rna.tf32.f32 %0, %1;" : "=r"(u) : "f"(x));
    return __uint_as_float(u);
}

#define MMA1688(c, a, b0, b1) \
    asm volatile("mma.sync.aligned.m16n8k8.row.col.f32.tf32.tf32.f32 " \
        "{%0,%1,%2,%3}, {%4,%5,%6,%7}, {%8,%9}, {%0,%1,%2,%3};" \
        : "+f"((c)[0]), "+f"((c)[1]), "+f"((c)[2]), "+f"((c)[3]) \
        : "r"((a)[0]), "r"((a)[1]), "r"((a)[2]), "r"((a)[3]), "r"(b0), "r"(b1))

#define LDSM4(r, a) \
    asm volatile("ldmatrix.sync.aligned.m8n8.x4.shared.b16 {%0,%1,%2,%3}, [%4];" \
        : "=r"((r)[0]), "=r"((r)[1]), "=r"((r)[2]), "=r"((r)[3]) : "r"(a))

#define CPASYNC16(dst, src) \
    asm volatile("cp.async.ca.shared.global [%0], [%1], 16;" :: "r"(dst), "l"(src))
#define CPASYNC16CG(dst, src) \
    asm volatile("cp.async.cg.shared.global [%0], [%1], 16;" :: "r"(dst), "l"(src))
#define CPCOMMIT() asm volatile("cp.async.commit_group;")
#define CPWAIT0()  asm volatile("cp.async.wait_group 0;")

// ============================================================
// Kernel A: Wh = X @ W (fp32 SIMT, exact for e); double-buffered (R10 body).
// Epilogue writes Wh TRANSPOSED (tf32-rounded) — R3-proven pattern.
// ============================================================
__global__ __launch_bounds__(256) void k_wh(const float* __restrict__ X,
                                            const float* __restrict__ W) {
    __shared__ float As[2][16][68];
    __shared__ float Bs[2][16][68];
    __shared__ float esh[64][17];

    const int t    = threadIdx.x;
    const int m0   = blockIdx.y * 64;
    const int n0   = blockIdx.x * 64;
    const int trow = t >> 4;
    const int tcol = t & 15;

    const int xi = t >> 2;
    const int xq = t & 3;
    const int wk = t >> 4;
    const int wj = (t & 15) << 2;

    float acc[4][4] = {};

    auto ldgX = [&](int k0) -> float4 {
        return *(const float4*)(X + (size_t)(m0 + xi) * FDIM + k0 + xq * 4);
    };
    auto stsX = [&](float4 v, int s) {
        As[s][xq*4+0][xi] = v.x; As[s][xq*4+1][xi] = v.y;
        As[s][xq*4+2][xi] = v.z; As[s][xq*4+3][xi] = v.w;
    };
    auto cpB = [&](int k0, int s) {
        CPASYNC16(smem_u32(&Bs[s][wk][wj]), W + (size_t)(k0 + wk) * HD + n0 + wj);
        CPCOMMIT();
    };

    {
        float4 v0 = ldgX(0);
        cpB(0, 0);
        stsX(v0, 0);
        CPWAIT0();
        __syncthreads();
    }

    for (int kt = 0; kt < 16; kt++) {
        const int cur = kt & 1;
        float4 nv;
        if (kt < 15) { nv = ldgX((kt + 1) * 16); cpB((kt + 1) * 16, cur ^ 1); }

        #pragma unroll
        for (int k = 0; k < 16; k++) {
            float a[4], b[4];
            #pragma unroll
            for (int i = 0; i < 4; i++) a[i] = As[cur][k][trow*4 + i];
            #pragma unroll
            for (int j = 0; j < 4; j++) b[j] = Bs[cur][k][tcol*4 + j];
            #pragma unroll
            for (int i = 0; i < 4; i++)
                #pragma unroll
                for (int j = 0; j < 4; j++)
                    acc[i][j] = fmaf(a[i], b[j], acc[i][j]);
        }
        __syncthreads();
        if (kt < 15) {
            stsX(nv, cur ^ 1);
            CPWAIT0();
            __syncthreads();
        }
    }

    // transposed tf32-rounded write: g_WhT[(b*HD + feat)][node]
    const int b     = m0 >> 11;
    const int node0 = (m0 & 2047) + trow * 4;
    #pragma unroll
    for (int j = 0; j < 4; j++) {
        int feat = n0 + tcol * 4 + j;
        float4 o;
        o.x = tf32_rna(acc[0][j]); o.y = tf32_rna(acc[1][j]);
        o.z = tf32_rna(acc[2][j]); o.w = tf32_rna(acc[3][j]);
        *(float4*)(g_WhT + ((size_t)(b * HD + feat)) * NNODES + node0) = o;
    }

    #pragma unroll
    for (int i = 0; i < 4; i++) {
        float s = acc[i][0]*acc[i][0] + acc[i][1]*acc[i][1]
                + acc[i][2]*acc[i][2] + acc[i][3]*acc[i][3];
        esh[trow*4 + i][tcol] = s;
    }
    __syncthreads();
    if (t < 64) {
        float s = 0.f;
        #pragma unroll
        for (int j = 0; j < 16; j++) s += esh[t][j];
        g_e[(size_t)(m0 + t) * HEADS + (n0 >> 6)] = s;
    }
}

// ============================================================
// Kernel B1: per-(b,h) softmax stats — 32 blocks
// ============================================================
__global__ __launch_bounds__(256) void k_stats() {
    const int b = blockIdx.x >> 2;
    const int h = blockIdx.x & 3;
    const int t = threadIdx.x;
    __shared__ float red[256];

    const float* eb = g_e + (size_t)b * NNODES * HEADS;

    float mx = -1e30f;
    for (int n = t; n < NNODES; n += 256)
        mx = fmaxf(mx, eb[n * HEADS + h]);
    red[t] = mx; __syncthreads();
    for (int s = 128; s > 0; s >>= 1) {
        if (t < s) red[t] = fmaxf(red[t], red[t + s]);
        __syncthreads();
    }
    mx = red[0]; __syncthreads();

    float sum = 0.f;
    for (int n = t; n < NNODES; n += 256)
        sum += __expf(eb[n * HEADS + h] - mx);
    red[t] = sum; __syncthreads();
    for (int s = 128; s > 0; s >>= 1) {
        if (t < s) red[t] += red[t + s];
        __syncthreads();
    }
    if (t == 0) {
        g_mx[blockIdx.x]  = mx;
        g_inv[blockIdx.x] = 1.0f / red[0];
    }
}

// ============================================================
// Kernel B2: att = head-mean of softmax — 64 blocks
// ============================================================
__global__ __launch_bounds__(256) void k_att() {
    int m = blockIdx.x * 256 + threadIdx.x;
    if (m >= MTOT) return;
    int b = m >> 11;
    const float* e4 = g_e + (size_t)m * HEADS;
    float a = 0.f;
    #pragma unroll
    for (int h = 0; h < HEADS; h++)
        a += __expf(e4[h] - g_mx[b * HEADS + h]) * g_inv[b * HEADS + h];
    g_att[m] = 0.25f * a;
}

// ============================================================
// Kernel C: tf32 mma.sync GEMM, ldmatrix feeds for BOTH operands
//   out = relu(att*(adj @ WhT^T) + bias)
// BM=128, BN=128, BK=32, 8 warps (4m x 2n), warp tile 32x64
// A tile [128 rows][36] (adj, m-major); B tile [128 rows][36] (WhT, n-major)
// Both fed via ldmatrix.x4 (A mapping HW-verified in R6; B identical structure)
// 2 CTAs/SM, 256 CTAs = 1 wave
// ============================================================
#define A_LD   36
#define B_OFF  18432                 // 128*36*4
#define STAGE  36864                 // 2 * 18432

__global__ void __launch_bounds__(256, 2)
k_out_tf32(const float* __restrict__ adj, const float* __restrict__ bias,
           float* __restrict__ out) {
    extern __shared__ char smem[];
    const uint32_t sb = smem_u32(smem);
    const int t    = threadIdx.x;
    const int lane = t & 31;
    const int wid  = t >> 5;
    const int b    = blockIdx.z;
    const int n0   = blockIdx.x * 128;   // n fastest -> adj tile L2 reuse
    const int m0   = blockIdx.y * 128;
    const int warp_m = wid & 3;          // 32 rows
    const int warp_n = wid >> 2;         // 64 cols

    const float* adjb = adj + (size_t)b * NNODES * NNODES;
    const float* WhTb = g_WhT + ((size_t)b * HD) * NNODES;

    float c[2][8][4];
    #pragma unroll
    for (int mt = 0; mt < 2; mt++)
        #pragma unroll
        for (int nt = 0; nt < 8; nt++)
            #pragma unroll
            for (int j = 0; j < 4; j++) c[mt][nt][j] = 0.f;

    auto load_stage = [&](int k0, uint32_t dst) {
        #pragma unroll
        for (int it = 0; it < 4; it++) {        // A: adj rows, 1024 chunks of 16B
            int idx = t + it * 256;
            int row = idx >> 3, u = idx & 7;
            CPASYNC16CG(dst + row * (A_LD*4) + u * 16,
                        adjb + (size_t)(m0 + row) * NNODES + k0 + u * 4);
        }
        #pragma unroll
        for (int it = 0; it < 4; it++) {        // B: WhT rows (n-major), 1024 chunks
            int idx = t + it * 256;
            int row = idx >> 3, u = idx & 7;
            CPASYNC16CG(dst + B_OFF + row * (A_LD*4) + u * 16,
                        WhTb + (size_t)(n0 + row) * NNODES + k0 + u * 4);
        }
        CPCOMMIT();
    };

    // ldmatrix lane addressing (R6-verified mapping)
    const int frow = ((lane >> 3) & 1) * 8 + (lane & 7);
    const int fcol = (lane >> 4) * 4;

    load_stage(0, sb);
    CPWAIT0();
    __syncthreads();

    for (int i = 0; i < 64; i++) {
        const uint32_t cur = sb + (uint32_t)(i & 1) * STAGE;
        if (i < 63) load_stage((i + 1) * 32, sb + (uint32_t)((i + 1) & 1) * STAGE);

        const uint32_t aBase = cur + (uint32_t)((warp_m * 32 + frow) * (A_LD*4) + fcol * 4);
        const uint32_t bBase = cur + B_OFF + (uint32_t)((warp_n * 64 + frow) * (A_LD*4) + fcol * 4);

        #pragma unroll
        for (int s = 0; s < 4; s++) {
            uint32_t a[2][4];
            LDSM4(a[0], aBase + s * 32);
            LDSM4(a[1], aBase + 16 * (A_LD*4) + s * 32);
            #pragma unroll
            for (int p = 0; p < 4; p++) {
                uint32_t bf[4];                  // bf0/bf1: b0 of ng=2p/2p+1; bf2/bf3: b1
                LDSM4(bf, bBase + p * 16 * (A_LD*4) + s * 32);
                MMA1688(c[0][2*p],   a[0], bf[0], bf[2]);
                MMA1688(c[1][2*p],   a[1], bf[0], bf[2]);
                MMA1688(c[0][2*p+1], a[0], bf[1], bf[3]);
                MMA1688(c[1][2*p+1], a[1], bf[1], bf[3]);
            }
        }

        if (i < 63) { CPWAIT0(); __syncthreads(); }
    }

    #pragma unroll
    for (int mt = 0; mt < 2; mt++) {
        int r0 = m0 + warp_m * 32 + mt * 16 + (lane >> 2);
        float att0 = g_att[b * NNODES + r0];
        float att1 = g_att[b * NNODES + r0 + 8];
        float* o0 = out + ((size_t)(b * NNODES + r0)) * HD;
        float* o1 = o0 + (size_t)8 * HD;
        #pragma unroll
        for (int nt = 0; nt < 8; nt++) {
            int col = n0 + warp_n * 64 + nt * 8 + 2 * (lane & 3);
            float2 bv = *(const float2*)(bias + col);
            float2 v0, v1;
            v0.x = fmaxf(fmaf(att0, c[mt][nt][0], bv.x), 0.f);
            v0.y = fmaxf(fmaf(att0, c[mt][nt][1], bv.y), 0.f);
            v1.x = fmaxf(fmaf(att1, c[mt][nt][2], bv.x), 0.f);
            v1.y = fmaxf(fmaf(att1, c[mt][nt][3], bv.y), 0.f);
            *(float2*)(o0 + col) = v0;
            *(float2*)(o1 + col) = v1;
        }
    }
}

// ============================================================
extern "C" void kernel_launch(void* const* d_in, const int* in_sizes, int n_in,
                              void* d_out, int out_size) {
    const float* features = (const float*)d_in[0];   // [8,2048,256]
    const float* adj      = (const float*)d_in[1];   // [8,2048,2048]
    const float* W        = (const float*)d_in[2];   // [256,256]
    const float* bias     = (const float*)d_in[3];   // [256]
    float* out = (float*)d_out;                      // [8,2048,256]

    cudaFuncSetAttribute(k_out_tf32, cudaFuncAttributeMaxDynamicSharedMemorySize, 2 * STAGE);

    k_wh      <<<dim3(HD/64, MTOT/64), 256>>>(features, W);
    k_stats   <<<BATCH*HEADS, 256>>>();
    k_att     <<<MTOT/256, 256>>>();
    k_out_tf32<<<dim3(HD/128, NNODES/128, BATCH), 256, 2 * STAGE>>>(adj, bias, out);
}

// round 15
// speedup vs baseline: 1.0504x; 1.0504x over previous
#include <cuda_runtime.h>
#include <cstdint>
#include <math.h>

#define BATCH   8
#define NNODES  2048
#define FDIM    256
#define HEADS   4
#define HD      256
#define MTOT    (BATCH*NNODES)

// ---- scratch ----
__device__ float g_Wh[(size_t)MTOT * HD];   // Wh, tf32-rounded, natural [node][feat]
__device__ float g_e[MTOT * HEADS];
__device__ float g_att[MTOT];
__device__ float g_mx[BATCH * HEADS];
__device__ float g_inv[BATCH * HEADS];

// ================= helpers =================
__device__ __forceinline__ uint32_t smem_u32(const void* p) {
    uint32_t a;
    asm("{ .reg .u64 t; cvta.to.shared.u64 t, %1; cvt.u32.u64 %0, t; }" : "=r"(a) : "l"(p));
    return a;
}
__device__ __forceinline__ float tf32_rna(float x) {
    uint32_t u;
    asm("cvt.rna.tf32.f32 %0, %1;" : "=r"(u) : "f"(x));
    return __uint_as_float(u);
}

#define MMA1688(c, a, b0, b1) \
    asm volatile("mma.sync.aligned.m16n8k8.row.col.f32.tf32.tf32.f32 " \
        "{%0,%1,%2,%3}, {%4,%5,%6,%7}, {%8,%9}, {%0,%1,%2,%3};" \
        : "+f"((c)[0]), "+f"((c)[1]), "+f"((c)[2]), "+f"((c)[3]) \
        : "r"((a)[0]), "r"((a)[1]), "r"((a)[2]), "r"((a)[3]), "r"(b0), "r"(b1))

#define CPASYNC16(dst, src) \
    asm volatile("cp.async.ca.shared.global [%0], [%1], 16;" :: "r"(dst), "l"(src))
#define CPASYNC16CG(dst, src) \
    asm volatile("cp.async.cg.shared.global [%0], [%1], 16;" :: "r"(dst), "l"(src))
#define CPCOMMIT()  asm volatile("cp.async.commit_group;")
#define CPWAIT0()   asm volatile("cp.async.wait_group 0;")
#define CPWAIT1()   asm volatile("cp.async.wait_group 1;")

// ============================================================
// Kernel A: Wh = X @ W (fp32 SIMT, exact for e); double-buffered (R10-verified)
// ============================================================
__global__ __launch_bounds__(256) void k_wh(const float* __restrict__ X,
                                            const float* __restrict__ W) {
    __shared__ float As[2][16][68];
    __shared__ float Bs[2][16][68];
    __shared__ float esh[64][17];

    const int t    = threadIdx.x;
    const int m0   = blockIdx.y * 64;
    const int n0   = blockIdx.x * 64;
    const int trow = t >> 4;
    const int tcol = t & 15;

    const int xi = t >> 2;
    const int xq = t & 3;
    const int wk = t >> 4;
    const int wj = (t & 15) << 2;

    float acc[4][4] = {};

    auto ldgX = [&](int k0) -> float4 {
        return *(const float4*)(X + (size_t)(m0 + xi) * FDIM + k0 + xq * 4);
    };
    auto stsX = [&](float4 v, int s) {
        As[s][xq*4+0][xi] = v.x; As[s][xq*4+1][xi] = v.y;
        As[s][xq*4+2][xi] = v.z; As[s][xq*4+3][xi] = v.w;
    };
    auto cpB = [&](int k0, int s) {
        CPASYNC16(smem_u32(&Bs[s][wk][wj]), W + (size_t)(k0 + wk) * HD + n0 + wj);
        CPCOMMIT();
    };

    {
        float4 v0 = ldgX(0);
        cpB(0, 0);
        stsX(v0, 0);
        CPWAIT0();
        __syncthreads();
    }

    for (int kt = 0; kt < 16; kt++) {
        const int cur = kt & 1;
        float4 nv;
        if (kt < 15) { nv = ldgX((kt + 1) * 16); cpB((kt + 1) * 16, cur ^ 1); }

        #pragma unroll
        for (int k = 0; k < 16; k++) {
            float a[4], b[4];
            #pragma unroll
            for (int i = 0; i < 4; i++) a[i] = As[cur][k][trow*4 + i];
            #pragma unroll
            for (int j = 0; j < 4; j++) b[j] = Bs[cur][k][tcol*4 + j];
            #pragma unroll
            for (int i = 0; i < 4; i++)
                #pragma unroll
                for (int j = 0; j < 4; j++)
                    acc[i][j] = fmaf(a[i], b[j], acc[i][j]);
        }
        __syncthreads();
        if (kt < 15) {
            stsX(nv, cur ^ 1);
            CPWAIT0();
            __syncthreads();
        }
    }

    #pragma unroll
    for (int i = 0; i < 4; i++) {
        int m = m0 + trow * 4 + i;
        float4 o;
        o.x = tf32_rna(acc[i][0]); o.y = tf32_rna(acc[i][1]);
        o.z = tf32_rna(acc[i][2]); o.w = tf32_rna(acc[i][3]);
        *(float4*)(g_Wh + (size_t)m * HD + n0 + tcol * 4) = o;
    }

    #pragma unroll
    for (int i = 0; i < 4; i++) {
        float s = acc[i][0]*acc[i][0] + acc[i][1]*acc[i][1]
                + acc[i][2]*acc[i][2] + acc[i][3]*acc[i][3];
        esh[trow*4 + i][tcol] = s;
    }
    __syncthreads();
    if (t < 64) {
        float s = 0.f;
        #pragma unroll
        for (int j = 0; j < 16; j++) s += esh[t][j];
        g_e[(size_t)(m0 + t) * HEADS + (n0 >> 6)] = s;
    }
}

// ============================================================
// Kernel B1: per-(b,h) softmax stats — 32 blocks
// ============================================================
__global__ __launch_bounds__(256) void k_stats() {
    const int b = blockIdx.x >> 2;
    const int h = blockIdx.x & 3;
    const int t = threadIdx.x;
    __shared__ float red[256];

    const float* eb = g_e + (size_t)b * NNODES * HEADS;

    float mx = -1e30f;
    for (int n = t; n < NNODES; n += 256)
        mx = fmaxf(mx, eb[n * HEADS + h]);
    red[t] = mx; __syncthreads();
    for (int s = 128; s > 0; s >>= 1) {
        if (t < s) red[t] = fmaxf(red[t], red[t + s]);
        __syncthreads();
    }
    mx = red[0]; __syncthreads();

    float sum = 0.f;
    for (int n = t; n < NNODES; n += 256)
        sum += __expf(eb[n * HEADS + h] - mx);
    red[t] = sum; __syncthreads();
    for (int s = 128; s > 0; s >>= 1) {
        if (t < s) red[t] += red[t + s];
        __syncthreads();
    }
    if (t == 0) {
        g_mx[blockIdx.x]  = mx;
        g_inv[blockIdx.x] = 1.0f / red[0];
    }
}

// ============================================================
// Kernel B2: att = head-mean of softmax — 64 blocks
// ============================================================
__global__ __launch_bounds__(256) void k_att() {
    int m = blockIdx.x * 256 + threadIdx.x;
    if (m >= MTOT) return;
    int b = m >> 11;
    const float* e4 = g_e + (size_t)m * HEADS;
    float a = 0.f;
    #pragma unroll
    for (int h = 0; h < HEADS; h++)
        a += __expf(e4[h] - g_mx[b * HEADS + h]) * g_inv[b * HEADS + h];
    g_att[m] = 0.25f * a;
}

// ============================================================
// Kernel C: tf32 mma.sync GEMM, 3-STAGE cp.async pipeline
//   out = relu(att*(adj @ Wh) + bias)
// BM=128, BN=128, BK=32, 8 warps (4m x 2n), warp tile 32x64 (R13-verified body)
// A [128][36] (bank 4r+kk), B [32][136] (bank 8kk+q) — conflict-free
// 3 stages x 35840B = 107.5KB/CTA; 2 CTAs/SM; wait_group(1) overlap
// ============================================================
#define A_LD   36
#define B_LD   136
#define B_OFF  18432                 // 128*36*4
#define STAGE  35840                 // 18432 + 32*136*4
#define NSTG   3

__global__ void __launch_bounds__(256, 2)
k_out_tf32(const float* __restrict__ adj, const float* __restrict__ bias,
           float* __restrict__ out) {
    extern __shared__ char smem[];
    const uint32_t sb = smem_u32(smem);
    const int t    = threadIdx.x;
    const int lane = t & 31;
    const int wid  = t >> 5;
    const int b    = blockIdx.z;
    const int n0   = blockIdx.x * 128;   // n fastest -> adj tile L2 reuse
    const int m0   = blockIdx.y * 128;
    const int warp_m = wid & 3;          // 32 rows
    const int warp_n = wid >> 2;         // 64 cols

    const float* adjb = adj + (size_t)b * NNODES * NNODES;
    const float* Whb  = g_Wh + ((size_t)b * NNODES) * HD;

    float c[2][8][4];
    #pragma unroll
    for (int mt = 0; mt < 2; mt++)
        #pragma unroll
        for (int nt = 0; nt < 8; nt++)
            #pragma unroll
            for (int j = 0; j < 4; j++) c[mt][nt][j] = 0.f;

    auto load_stage = [&](int k0, uint32_t dst) {
        #pragma unroll
        for (int it = 0; it < 4; it++) {        // A: 128x32 = 1024 chunks of 16B
            int idx = t + it * 256;
            int row = idx >> 3, u = idx & 7;
            CPASYNC16CG(dst + row * (A_LD*4) + u * 16,
                        adjb + (size_t)(m0 + row) * NNODES + k0 + u * 4);
        }
        #pragma unroll
        for (int it = 0; it < 4; it++) {        // B: 32x128 = 1024 chunks of 16B
            int idx = t + it * 256;
            int row = idx >> 5, u = idx & 31;
            CPASYNC16CG(dst + B_OFF + row * (B_LD*4) + u * 16,
                        Whb + (size_t)(k0 + row) * HD + n0 + u * 4);
        }
        CPCOMMIT();
    };

    // ---- prologue: stages 0,1 in flight ----
    load_stage(0, sb);
    load_stage(32, sb + STAGE);

    int cur = 0;                       // stage index of k-tile i
    int nxt = 2;                       // stage index for k-tile i+2

    for (int i = 0; i < 64; i++) {
        if (i < 63) { CPWAIT1(); } else { CPWAIT0(); }
        __syncthreads();

        if (i < 62) {
            load_stage((i + 2) * 32, sb + (uint32_t)nxt * STAGE);
            nxt = (nxt == 2) ? 0 : nxt + 1;
        }

        const float* Asm = (const float*)(smem + (size_t)cur * STAGE);
        const float* Bsm = (const float*)(smem + (size_t)cur * STAGE + B_OFF);
        cur = (cur == 2) ? 0 : cur + 1;

        #pragma unroll
        for (int s = 0; s < 4; s++) {
            const int kk = s * 8 + (lane & 3);
            uint32_t a[2][4];
            #pragma unroll
            for (int mt = 0; mt < 2; mt++) {
                int r = warp_m * 32 + mt * 16 + (lane >> 2);
                a[mt][0] = __float_as_uint(Asm[r * A_LD + kk]);        // raw bits: HW tf32 trunc
                a[mt][1] = __float_as_uint(Asm[(r + 8) * A_LD + kk]);
                a[mt][2] = __float_as_uint(Asm[r * A_LD + kk + 4]);
                a[mt][3] = __float_as_uint(Asm[(r + 8) * A_LD + kk + 4]);
            }
            #pragma unroll
            for (int ng = 0; ng < 8; ng++) {
                int n = warp_n * 64 + ng * 8 + (lane >> 2);
                uint32_t b0 = __float_as_uint(Bsm[kk * B_LD + n]);     // pre-rounded (RNA)
                uint32_t b1 = __float_as_uint(Bsm[(kk + 4) * B_LD + n]);
                MMA1688(c[0][ng], a[0], b0, b1);
                MMA1688(c[1][ng], a[1], b0, b1);
            }
        }
    }

    #pragma unroll
    for (int mt = 0; mt < 2; mt++) {
        int r0 = m0 + warp_m * 32 + mt * 16 + (lane >> 2);
        float att0 = g_att[b * NNODES + r0];
        float att1 = g_att[b * NNODES + r0 + 8];
        float* o0 = out + ((size_t)(b * NNODES + r0)) * HD;
        float* o1 = o0 + (size_t)8 * HD;
        #pragma unroll
        for (int nt = 0; nt < 8; nt++) {
            int col = n0 + warp_n * 64 + nt * 8 + 2 * (lane & 3);
            float2 bv = *(const float2*)(bias + col);
            float2 v0, v1;
            v0.x = fmaxf(fmaf(att0, c[mt][nt][0], bv.x), 0.f);
            v0.y = fmaxf(fmaf(att0, c[mt][nt][1], bv.y), 0.f);
            v1.x = fmaxf(fmaf(att1, c[mt][nt][2], bv.x), 0.f);
            v1.y = fmaxf(fmaf(att1, c[mt][nt][3], bv.y), 0.f);
            *(float2*)(o0 + col) = v0;
            *(float2*)(o1 + col) = v1;
        }
    }
}

// ============================================================
extern "C" void kernel_launch(void* const* d_in, const int* in_sizes, int n_in,
                              void* d_out, int out_size) {
    const float* features = (const float*)d_in[0];   // [8,2048,256]
    const float* adj      = (const float*)d_in[1];   // [8,2048,2048]
    const float* W        = (const float*)d_in[2];   // [256,256]
    const float* bias     = (const float*)d_in[3];   // [256]
    float* out = (float*)d_out;                      // [8,2048,256]

    cudaFuncSetAttribute(k_out_tf32, cudaFuncAttributeMaxDynamicSharedMemorySize, NSTG * STAGE);

    k_wh      <<<dim3(HD/64, MTOT/64), 256>>>(features, W);
    k_stats   <<<BATCH*HEADS, 256>>>();
    k_att     <<<MTOT/256, 256>>>();
    k_out_tf32<<<dim3(HD/128, NNODES/128, BATCH), 256, NSTG * STAGE>>>(adj, bias, out);
}

// round 17
// speedup vs baseline: 1.0601x; 1.0093x over previous
#include <cuda_runtime.h>
#include <cstdint>
#include <math.h>

#define BATCH   8
#define NNODES  2048
#define FDIM    256
#define HEADS   4
#define HD      256
#define MTOT    (BATCH*NNODES)

// ---- scratch ----
__device__ float g_Wh[(size_t)MTOT * HD];   // Wh, tf32-rounded, natural [node][feat]
__device__ float g_e[MTOT * HEADS];
__device__ float g_att[MTOT];
__device__ float g_mx[BATCH * HEADS];
__device__ float g_inv[BATCH * HEADS];

// ================= helpers =================
__device__ __forceinline__ uint32_t smem_u32(const void* p) {
    uint32_t a;
    asm("{ .reg .u64 t; cvta.to.shared.u64 t, %1; cvt.u32.u64 %0, t; }" : "=r"(a) : "l"(p));
    return a;
}
__device__ __forceinline__ float tf32_rna(float x) {
    uint32_t u;
    asm("cvt.rna.tf32.f32 %0, %1;" : "=r"(u) : "f"(x));
    return __uint_as_float(u);
}

#define MMA1688(c, a, b0, b1) \
    asm volatile("mma.sync.aligned.m16n8k8.row.col.f32.tf32.tf32.f32 " \
        "{%0,%1,%2,%3}, {%4,%5,%6,%7}, {%8,%9}, {%0,%1,%2,%3};" \
        : "+f"((c)[0]), "+f"((c)[1]), "+f"((c)[2]), "+f"((c)[3]) \
        : "r"((a)[0]), "r"((a)[1]), "r"((a)[2]), "r"((a)[3]), "r"(b0), "r"(b1))

#define CPASYNC16(dst, src) \
    asm volatile("cp.async.ca.shared.global [%0], [%1], 16;" :: "r"(dst), "l"(src))
#define CPASYNC16CG(dst, src) \
    asm volatile("cp.async.cg.shared.global [%0], [%1], 16;" :: "r"(dst), "l"(src))
#define CPCOMMIT() asm volatile("cp.async.commit_group;")
#define CPWAIT0()  asm volatile("cp.async.wait_group 0;")

// ============================================================
// Kernel A: Wh = X @ W (fp32 SIMT, exact for e); double-buffered.
// BM=128, BN=64, BK=16, 256 threads, 8x4 microtile.
// k-major As [16][136] (544B rows, 16B-aligned): a-feed = 2x LDS.128 broadcast.
// Bs [16][72] (288B rows): b-feed = 1x LDS.128, conflict-free (2 phases).
// ============================================================
__global__ __launch_bounds__(256) void k_wh(const float* __restrict__ X,
                                            const float* __restrict__ W) {
    __shared__ float As[2][16][136];
    __shared__ float Bs[2][16][72];
    __shared__ float esh[128][17];

    const int t    = threadIdx.x;
    const int m0   = blockIdx.y * 128;
    const int n0   = blockIdx.x * 64;
    const int trow = t >> 4;          // 0..15 -> rows trow*8..+7
    const int tcol = t & 15;          // cols tcol*4..+3

    // loader mapping
    const int xi = t >> 1;            // row 0..127
    const int xq = t & 1;             // k-half: quads xq*2, xq*2+1
    const int wk = t >> 4;            // 0..15
    const int wj = (t & 15) << 2;     // col*4

    float acc[8][4] = {};
    float4 nv[2];

    auto ldgX = [&](int k0) {
        const float* p = X + (size_t)(m0 + xi) * FDIM + k0 + xq * 8;
        nv[0] = *(const float4*)p;
        nv[1] = *(const float4*)(p + 4);
    };
    auto stsX = [&](int s) {
        #pragma unroll
        for (int q = 0; q < 2; q++) {
            float v[4] = {q ? nv[1].x : nv[0].x, q ? nv[1].y : nv[0].y,
                          q ? nv[1].z : nv[0].z, q ? nv[1].w : nv[0].w};
            #pragma unroll
            for (int j = 0; j < 4; j++)
                As[s][xq*8 + q*4 + j][xi] = v[j];
        }
    };
    auto cpB = [&](int k0, int s) {
        CPASYNC16(smem_u32(&Bs[s][wk][wj]), W + (size_t)(k0 + wk) * HD + n0 + wj);
        CPCOMMIT();
    };

    // ---- prologue ----
    {
        ldgX(0);
        cpB(0, 0);
        stsX(0);
        CPWAIT0();
        __syncthreads();
    }

    // ---- main loop: 16 k-tiles, double-buffered ----
    for (int kt = 0; kt < 16; kt++) {
        const int cur = kt & 1;
        if (kt < 15) { ldgX((kt + 1) * 16); cpB((kt + 1) * 16, cur ^ 1); }

        #pragma unroll
        for (int k = 0; k < 16; k++) {
            float4 a0 = *(const float4*)&As[cur][k][trow * 8];
            float4 a1 = *(const float4*)&As[cur][k][trow * 8 + 4];
            float4 b4 = *(const float4*)&Bs[cur][k][tcol * 4];
            float a[8] = {a0.x, a0.y, a0.z, a0.w, a1.x, a1.y, a1.z, a1.w};
            float b[4] = {b4.x, b4.y, b4.z, b4.w};
            #pragma unroll
            for (int i = 0; i < 8; i++)
                #pragma unroll
                for (int j = 0; j < 4; j++)
                    acc[i][j] = fmaf(a[i], b[j], acc[i][j]);
        }
        __syncthreads();
        if (kt < 15) {
            stsX(cur ^ 1);
            CPWAIT0();
            __syncthreads();
        }
    }

    // coalesced natural-layout write, tf32-rounded
    #pragma unroll
    for (int i = 0; i < 8; i++) {
        int m = m0 + trow * 8 + i;
        float4 o;
        o.x = tf32_rna(acc[i][0]); o.y = tf32_rna(acc[i][1]);
        o.z = tf32_rna(acc[i][2]); o.w = tf32_rna(acc[i][3]);
        *(float4*)(g_Wh + (size_t)m * HD + n0 + tcol * 4) = o;
    }

    #pragma unroll
    for (int i = 0; i < 8; i++) {
        float s = acc[i][0]*acc[i][0] + acc[i][1]*acc[i][1]
                + acc[i][2]*acc[i][2] + acc[i][3]*acc[i][3];
        esh[trow * 8 + i][tcol] = s;
    }
    __syncthreads();
    if (t < 128) {
        float s = 0.f;
        #pragma unroll
        for (int j = 0; j < 16; j++) s += esh[t][j];
        g_e[(size_t)(m0 + t) * HEADS + (n0 >> 6)] = s;
    }
}

// ============================================================
// Kernel B1: per-(b,h) softmax stats — 32 blocks
// ============================================================
__global__ __launch_bounds__(256) void k_stats() {
    const int b = blockIdx.x >> 2;
    const int h = blockIdx.x & 3;
    const int t = threadIdx.x;
    __shared__ float red[256];

    const float* eb = g_e + (size_t)b * NNODES * HEADS;

    float mx = -1e30f;
    for (int n = t; n < NNODES; n += 256)
        mx = fmaxf(mx, eb[n * HEADS + h]);
    red[t] = mx; __syncthreads();
    for (int s = 128; s > 0; s >>= 1) {
        if (t < s) red[t] = fmaxf(red[t], red[t + s]);
        __syncthreads();
    }
    mx = red[0]; __syncthreads();

    float sum = 0.f;
    for (int n = t; n < NNODES; n += 256)
        sum += __expf(eb[n * HEADS + h] - mx);
    red[t] = sum; __syncthreads();
    for (int s = 128; s > 0; s >>= 1) {
        if (t < s) red[t] += red[t + s];
        __syncthreads();
    }
    if (t == 0) {
        g_mx[blockIdx.x]  = mx;
        g_inv[blockIdx.x] = 1.0f / red[0];
    }
}

// ============================================================
// Kernel B2: att = head-mean of softmax — 64 blocks
// ============================================================
__global__ __launch_bounds__(256) void k_att() {
    int m = blockIdx.x * 256 + threadIdx.x;
    if (m >= MTOT) return;
    int b = m >> 11;
    const float* e4 = g_e + (size_t)m * HEADS;
    float a = 0.f;
    #pragma unroll
    for (int h = 0; h < HEADS; h++)
        a += __expf(e4[h] - g_mx[b * HEADS + h]) * g_inv[b * HEADS + h];
    g_att[m] = 0.25f * a;
}

// ============================================================
// Kernel C: tf32 mma.sync GEMM  (EXACT R13 configuration — 183.0us verified)
//   out = relu(att*(adj @ Wh) + bias)
// BM=128, BN=128, BK=32, 8 warps (4m x 2n), warp tile 32x64, 2-stage
// A [128][36] (bank 4r+kk), B [32][136] (bank 8kk+q) — conflict-free
// 2 CTAs/SM, 256 CTAs = 1 wave
// ============================================================
#define A_LD   36
#define B_LD   136
#define B_OFF  18432                 // 128*36*4
#define STAGE  35840                 // 18432 + 32*136*4

__global__ void __launch_bounds__(256, 2)
k_out_tf32(const float* __restrict__ adj, const float* __restrict__ bias,
           float* __restrict__ out) {
    extern __shared__ char smem[];
    const uint32_t sb = smem_u32(smem);
    const int t    = threadIdx.x;
    const int lane = t & 31;
    const int wid  = t >> 5;
    const int b    = blockIdx.z;
    const int n0   = blockIdx.x * 128;   // n fastest -> adj tile L2 reuse
    const int m0   = blockIdx.y * 128;
    const int warp_m = wid & 3;          // 32 rows
    const int warp_n = wid >> 2;         // 64 cols

    const float* adjb = adj + (size_t)b * NNODES * NNODES;
    const float* Whb  = g_Wh + ((size_t)b * NNODES) * HD;

    float c[2][8][4];
    #pragma unroll
    for (int mt = 0; mt < 2; mt++)
        #pragma unroll
        for (int nt = 0; nt < 8; nt++)
            #pragma unroll
            for (int j = 0; j < 4; j++) c[mt][nt][j] = 0.f;

    auto load_stage = [&](int k0, uint32_t dst) {
        #pragma unroll
        for (int it = 0; it < 4; it++) {        // A: 128x32 = 1024 chunks of 16B
            int idx = t + it * 256;
            int row = idx >> 3, u = idx & 7;
            CPASYNC16CG(dst + row * (A_LD*4) + u * 16,
                        adjb + (size_t)(m0 + row) * NNODES + k0 + u * 4);
        }
        #pragma unroll
        for (int it = 0; it < 4; it++) {        // B: 32x128 = 1024 chunks of 16B
            int idx = t + it * 256;
            int row = idx >> 5, u = idx & 31;
            CPASYNC16CG(dst + B_OFF + row * (B_LD*4) + u * 16,
                        Whb + (size_t)(k0 + row) * HD + n0 + u * 4);
        }
        CPCOMMIT();
    };

    load_stage(0, sb);
    CPWAIT0();
    __syncthreads();

    for (int i = 0; i < 64; i++) {
        const uint32_t cur = (uint32_t)(i & 1) * STAGE;
        if (i < 63) load_stage((i + 1) * 32, sb + (uint32_t)((i + 1) & 1) * STAGE);

        const float* Asm = (const float*)(smem + cur);
        const float* Bsm = (const float*)(smem + cur + B_OFF);

        #pragma unroll
        for (int s = 0; s < 4; s++) {
            const int kk = s * 8 + (lane & 3);
            uint32_t a[2][4];
            #pragma unroll
            for (int mt = 0; mt < 2; mt++) {
                int r = warp_m * 32 + mt * 16 + (lane >> 2);
                a[mt][0] = __float_as_uint(Asm[r * A_LD + kk]);        // raw bits: HW tf32 trunc
                a[mt][1] = __float_as_uint(Asm[(r + 8) * A_LD + kk]);
                a[mt][2] = __float_as_uint(Asm[r * A_LD + kk + 4]);
                a[mt][3] = __float_as_uint(Asm[(r + 8) * A_LD + kk + 4]);
            }
            #pragma unroll
            for (int ng = 0; ng < 8; ng++) {
                int n = warp_n * 64 + ng * 8 + (lane >> 2);
                uint32_t b0 = __float_as_uint(Bsm[kk * B_LD + n]);     // pre-rounded (RNA)
                uint32_t b1 = __float_as_uint(Bsm[(kk + 4) * B_LD + n]);
                MMA1688(c[0][ng], a[0], b0, b1);
                MMA1688(c[1][ng], a[1], b0, b1);
            }
        }

        if (i < 63) { CPWAIT0(); __syncthreads(); }
    }

    #pragma unroll
    for (int mt = 0; mt < 2; mt++) {
        int r0 = m0 + warp_m * 32 + mt * 16 + (lane >> 2);
        float att0 = g_att[b * NNODES + r0];
        float att1 = g_att[b * NNODES + r0 + 8];
        float* o0 = out + ((size_t)(b * NNODES + r0)) * HD;
        float* o1 = o0 + (size_t)8 * HD;
        #pragma unroll
        for (int nt = 0; nt < 8; nt++) {
            int col = n0 + warp_n * 64 + nt * 8 + 2 * (lane & 3);
            float2 bv = *(const float2*)(bias + col);
            float2 v0, v1;
            v0.x = fmaxf(fmaf(att0, c[mt][nt][0], bv.x), 0.f);
            v0.y = fmaxf(fmaf(att0, c[mt][nt][1], bv.y), 0.f);
            v1.x = fmaxf(fmaf(att1, c[mt][nt][2], bv.x), 0.f);
            v1.y = fmaxf(fmaf(att1, c[mt][nt][3], bv.y), 0.f);
            *(float2*)(o0 + col) = v0;
            *(float2*)(o1 + col) = v1;
        }
    }
}

// ============================================================
extern "C" void kernel_launch(void* const* d_in, const int* in_sizes, int n_in,
                              void* d_out, int out_size) {
    const float* features = (const float*)d_in[0];   // [8,2048,256]
    const float* adj      = (const float*)d_in[1];   // [8,2048,2048]
    const float* W        = (const float*)d_in[2];   // [256,256]
    const float* bias     = (const float*)d_in[3];   // [256]
    float* out = (float*)d_out;                      // [8,2048,256]

    cudaFuncSetAttribute(k_out_tf32, cudaFuncAttributeMaxDynamicSharedMemorySize, 2 * STAGE);

    k_wh      <<<dim3(HD/64, MTOT/128), 256>>>(features, W);
    k_stats   <<<BATCH*HEADS, 256>>>();
    k_att     <<<MTOT/256, 256>>>();
    k_out_tf32<<<dim3(HD/128, NNODES/128, BATCH), 256, 2 * STAGE>>>(adj, bias, out);
}